// round 17
// baseline (speedup 1.0000x reference)
#include <cuda_runtime.h>
#include <stdint.h>

#define IMH 1024
#define IMW 1024
#define NB  8
#define WPR 32   // 32-bit words per image row

__device__ uint32_t g_strong[NB * IMH * WPR];
__device__ uint32_t g_weak[NB * IMH * WPR];

#define ROWS1 32
#define ROWLEN 1032          // data col g -> idx 4+g; zero guards at idx 3, 1028

#define HI2 (0.3f * 0.3f)
#define LO2 (0.1f * 0.1f)

// load 6-float window (cols cx-1 .. cx+4): scalar + float4 + scalar
#define LD6(P, W) do { \
    const float* _p = (P); \
    W[0] = _p[3 + cx]; \
    float4 _v = *(const float4*)(_p + 4 + cx); \
    W[1] = _v.x; W[2] = _v.y; W[3] = _v.z; W[4] = _v.w; \
    W[5] = _p[8 + cx]; \
} while(0)

// verbatim 9-tap gaussian for 4 outputs from 6-col windows
#define BLUR4(A, M, D, out) do { \
    (out).x = 0.0625f*A[0] + 0.125f*A[1] + 0.0625f*A[2] \
            + 0.125f *M[0] + 0.25f *M[1] + 0.125f *M[2] \
            + 0.0625f*D[0] + 0.125f*D[1] + 0.0625f*D[2]; \
    (out).y = 0.0625f*A[1] + 0.125f*A[2] + 0.0625f*A[3] \
            + 0.125f *M[1] + 0.25f *M[2] + 0.125f *M[3] \
            + 0.0625f*D[1] + 0.125f*D[2] + 0.0625f*D[3]; \
    (out).z = 0.0625f*A[2] + 0.125f*A[3] + 0.0625f*A[4] \
            + 0.125f *M[2] + 0.25f *M[3] + 0.125f *M[4] \
            + 0.0625f*D[2] + 0.125f*D[3] + 0.0625f*D[4]; \
    (out).w = 0.0625f*A[3] + 0.125f*A[4] + 0.0625f*A[5] \
            + 0.125f *M[3] + 0.25f *M[4] + 0.125f *M[5] \
            + 0.0625f*D[3] + 0.125f*D[4] + 0.0625f*D[5]; \
} while(0)

// verbatim sobel, SQUARED magnitude + 2-bit bins packed (static indexing only)
#define SOBEL4(U, C, D, magv, binpk) do { \
    float _mm[4]; \
    _Pragma("unroll") \
    for (int j = 0; j < 4; j++) { \
        float gx = (U[j+2] - U[j]) + 2.0f * (C[j+2] - C[j]) + (D[j+2] - D[j]); \
        float gy = (D[j] - U[j]) + 2.0f * (D[j+1] - U[j+1]) + (D[j+2] - U[j+2]); \
        _mm[j] = gx * gx + gy * gy; \
        float ax = fabsf(gx), ay = fabsf(gy); \
        bool ss = ((__float_as_uint(gx) ^ __float_as_uint(gy)) >> 31) == 0u; \
        int bn = (ay < 0.41421356237309503f * ax) ? 0 : \
                 (ay >= 2.414213562373095f  * ax) ? 2 : (ss ? 1 : 3); \
        binpk |= (unsigned)bn << (2 * j); \
    } \
    (magv) = make_float4(_mm[0], _mm[1], _mm[2], _mm[3]); \
} while(0)

// NMS + threshold + pack; mag rows indexed DIRECTLY in smem (dynamic j+-dc)
#define NMS4(SU, SC, SD, BINP, ROWN) do { \
    const float* mu = s_mag[SU] + 4 + cx; \
    const float* mc = s_mag[SC] + 4 + cx; \
    const float* md = s_mag[SD] + 4 + cx; \
    unsigned vs = 0u, vw = 0u; \
    _Pragma("unroll") \
    for (int j = 0; j < 4; j++) { \
        float m = mc[j]; \
        int bin = (int)(((BINP) >> (2 * j)) & 3u); \
        int dc = (bin <= 1) ? 1 : ((bin == 2) ? 0 : -1); \
        const float* p1 = (bin == 0) ? mc : mu; \
        const float* p2 = (bin == 0) ? mc : md; \
        float n1 = p1[j + dc], n2 = p2[j - dc]; \
        float sup = (m >= n1 && m >= n2) ? m : 0.f; \
        if (sup >= HI2) vs |= (1u << j); \
        if (sup >= LO2 && sup < HI2) vw |= (1u << j); \
    } \
    unsigned msk = 0xFFu << (lane & 24); \
    int sh = 4 * (t & 7); \
    unsigned ws = __reduce_or_sync(msk, vs << sh); \
    unsigned ww = __reduce_or_sync(msk, vw << sh); \
    if ((t & 7) == 0) { \
        int idx = (b * IMH + (ROWN)) * WPR + (t >> 3); \
        g_strong[idx] = ws; g_weak[idx] = ww; } \
} while(0)

// One pair-iteration at compile-time slot S = slot(r), slot(n)=(n-(y0-3)) mod 6.
// Stores raw(r),raw(r+1), bl(r-3),bl(r-2), mag(r-6),mag(r-5); sync;
// prefetch raw(r+2,r+3); blur rows r-1,r; sobel+bin rows r-4,r-3;
// NMS rows r-7,r-6. Depth-6 rings: every overwritten row's last reader ran
// 2 pair-iterations earlier, behind an intervening barrier (same proof as R16).
#define BODY(S) do { \
    ((float4*)(s_raw[(S+0)%6] + 4))[t] = rv0; \
    ((float4*)(s_raw[(S+1)%6] + 4))[t] = rv1; \
    ((float4*)(s_bl [(S+3)%6] + 4))[t] = blp0; \
    ((float4*)(s_bl [(S+4)%6] + 4))[t] = blp1; \
    ((float4*)(s_mag[(S+0)%6] + 4))[t] = magp0; \
    ((float4*)(s_mag[(S+1)%6] + 4))[t] = magp1; \
    __syncthreads(); \
    { float4 _a = Z4, _b2 = Z4; \
      if ((unsigned)(r + 2) < IMH) _a  = *(const float4*)(img + (size_t)(r + 2) * IMW + cx); \
      if ((unsigned)(r + 3) < IMH) _b2 = *(const float4*)(img + (size_t)(r + 3) * IMW + cx); \
      rv0 = _a; rv1 = _b2; } \
    { float q0[6], q1[6], q2[6], q3[6]; \
      LD6(s_raw[(S+4)%6], q0); LD6(s_raw[(S+5)%6], q1); \
      LD6(s_raw[(S+0)%6], q2); LD6(s_raw[(S+1)%6], q3); \
      float4 bn0 = Z4, bn1 = Z4; \
      if (r >= y0 - 1 && (unsigned)(r - 1) < IMH) BLUR4(q0, q1, q2, bn0); \
      if (r >= y0 - 2 && (unsigned)(r)     < IMH) BLUR4(q1, q2, q3, bn1); \
      blp0 = bn0; blp1 = bn1; } \
    { float v0[6], v1[6], v2[6], v3[6]; \
      LD6(s_bl[(S+1)%6], v0); LD6(s_bl[(S+2)%6], v1); \
      LD6(s_bl[(S+3)%6], v2); LD6(s_bl[(S+4)%6], v3); \
      float4 mg0 = Z4, mg1 = Z4; \
      unsigned binA = 0u, binB = 0u; \
      if (r >= y0 + 3 && (unsigned)(r - 4) < IMH) SOBEL4(v0, v1, v2, mg0, binA); \
      if (r >= y0 + 2 && (unsigned)(r - 3) < IMH) SOBEL4(v1, v2, v3, mg1, binB); \
      if (r >= y0 + 7 && r < y0 + ROWS1 + 7) NMS4((S+4)%6, (S+5)%6, (S+0)%6, binB2, (r - 7)); \
      if (r >= y0 + 6 && r < y0 + ROWS1 + 6) NMS4((S+5)%6, (S+0)%6, (S+1)%6, binA1, (r - 6)); \
      magp0 = mg0; magp1 = mg1; \
      binB2 = binB1; binB1 = binB; binA1 = binA; } \
    r += 2; \
} while(0)

// ---------------------------------------------------------------------------
// K1: 2-row-paired rolling pipeline, 256 threads x 4 cols, full-width rows.
// Vectorized smem traffic (~7 LSU ops/px vs 18), 8-warp barriers, depth-6
// rings, squared-magnitude NMS. Up to 3 blocks/SM (74.3KB smem, 85-reg cap).
// ---------------------------------------------------------------------------
__global__ void __launch_bounds__(256, 3) canny_front(const float* __restrict__ in)
{
    __shared__ __align__(16) float s_raw[6][ROWLEN];
    __shared__ __align__(16) float s_bl [6][ROWLEN];
    __shared__ __align__(16) float s_mag[6][ROWLEN];

    const int t    = threadIdx.x;             // 0..255
    const int lane = t & 31;
    const int b    = blockIdx.y;
    const int y0   = blockIdx.x * ROWS1;
    const float* img = in + (size_t)b * IMH * IMW;
    const int cx = 4 * t;                     // first of 4 owned columns

    const float4 Z4 = make_float4(0.f, 0.f, 0.f, 0.f);

    // zero guards: 3 arrays x 6 slots x 2 cells = 36
    if (t < 36) {
        int arr = t / 12, rem = t % 12, s = rem % 6;
        int pos = (rem / 6) ? 1028 : 3;
        float* base = (arr == 0) ? &s_raw[0][0] : (arr == 1) ? &s_bl[0][0] : &s_mag[0][0];
        base[s * ROWLEN + pos] = 0.f;
    }

    float4 blp0 = Z4, blp1 = Z4;     // bl(r-3), bl(r-2) pending
    float4 magp0 = Z4, magp1 = Z4;   // mag(r-6), mag(r-5) pending
    unsigned binA1 = 0u, binB1 = 0u, binB2 = 0u;

    int r = y0 - 3;
    float4 rv0 = Z4, rv1 = Z4;
    if ((unsigned)r       < IMH) rv0 = *(const float4*)(img + (size_t)r       * IMW + cx);
    if ((unsigned)(r + 1) < IMH) rv1 = *(const float4*)(img + (size_t)(r + 1) * IMW + cx);

    // 21 pair-iterations = 7 x (slots 0,2,4)
    #pragma unroll 1
    for (int jj = 0; jj < 7; ++jj) {
        BODY(0);
        BODY(2);
        BODY(4);
    }
}

// ---------------------------------------------------------------------------
// K2: hysteresis, rows in registers (8/warp), shuffle horizontal neighbors,
// smem exchange for strip-boundary rows, ONE barrier/iter fused with exact
// convergence early-exit (__syncthreads_or). Tile 64 rows (16+32+16), grid
// 32x8. Float expansion via 16-entry float4 LUT.
// ---------------------------------------------------------------------------
__global__ void __launch_bounds__(256) canny_hyst(float* __restrict__ out)
{
    __shared__ uint32_t sm_top[2][8][32];
    __shared__ uint32_t sm_bot[2][8][32];
    __shared__ uint32_t Efin[32][32];
    __shared__ float4   lut4[16];

    const int tid  = threadIdx.x;
    const int lane = tid & 31;
    const int w    = tid >> 5;
    const int by   = blockIdx.x;
    const int b    = blockIdx.y;
    const int r0   = by * 32;

    if (tid < 16) {
        lut4[tid] = make_float4((float)(tid & 1), (float)((tid >> 1) & 1),
                                (float)((tid >> 2) & 1), (float)((tid >> 3) & 1));
    }

    uint32_t e[8], wk[8];
    #pragma unroll
    for (int k = 0; k < 8; k++) {
        int gr = r0 - 16 + 8 * w + k;
        uint32_t ev = 0u, wv = 0u;
        if ((unsigned)gr < IMH) {
            int idx = (b * IMH + gr) * WPR + lane;
            ev = g_strong[idx];
            wv = g_weak[idx];
        }
        e[k] = ev; wk[k] = wv;
    }

    unsigned changed = 1u;
    #pragma unroll 1
    for (int it = 0; it < 16; ++it) {
        const int p = it & 1;
        sm_top[p][w][lane] = e[0];
        sm_bot[p][w][lane] = e[7];
        int any = __syncthreads_or((int)(changed != 0u));
        if (!any) break;
        uint32_t above = (w > 0) ? sm_bot[p][w - 1][lane] : 0u;
        uint32_t below = (w < 7) ? sm_top[p][w + 1][lane] : 0u;

        uint32_t rowv[10];
        rowv[0] = above;
        #pragma unroll
        for (int k = 0; k < 8; k++) rowv[k + 1] = e[k];
        rowv[9] = below;

        uint32_t h[10];
        #pragma unroll
        for (int k = 0; k < 10; k++) {
            uint32_t m = rowv[k];
            uint32_t l  = __shfl_up_sync(0xffffffffu, m, 1);
            uint32_t rr = __shfl_down_sync(0xffffffffu, m, 1);
            if (lane == 0)  l = 0u;
            if (lane == 31) rr = 0u;
            h[k] = m | (m << 1) | (m >> 1) | (l >> 31) | (rr << 31);
        }
        changed = 0u;
        #pragma unroll
        for (int k = 0; k < 8; k++) {
            uint32_t ne = e[k] | (wk[k] & (h[k] | h[k + 1] | h[k + 2]));
            changed |= (ne ^ e[k]);
            e[k] = ne;
        }
    }

    #pragma unroll
    for (int k = 0; k < 8; k++) {
        int dr = 8 * w + k;
        if (dr >= 16 && dr < 48) Efin[dr - 16][lane] = e[k];
    }
    __syncthreads();

    float4* o = (float4*)(out + (size_t)b * IMH * IMW + (size_t)r0 * IMW);
    #pragma unroll
    for (int u = tid; u < 32 * 256; u += 256) {
        int row = u >> 8;
        int q   = u & 255;
        int colpx = q << 2;
        uint32_t word = Efin[row][colpx >> 5];
        o[(row << 8) + q] = lut4[(word >> (colpx & 31)) & 15u];
    }
}

extern "C" void kernel_launch(void* const* d_in, const int* in_sizes, int n_in,
                              void* d_out, int out_size)
{
    const float* in = (const float*)d_in[0];
    float* out = (float*)d_out;

    dim3 g1(IMH / ROWS1, NB);     // 32 x 8 = 256 blocks
    canny_front<<<g1, 256>>>(in);

    dim3 g2(32, NB);              // 32 x 8 = 256 blocks
    canny_hyst<<<g2, 256>>>(out);
}